// round 2
// baseline (speedup 1.0000x reference)
#include <cuda_runtime.h>
#include <math.h>

#define BB 16
#define CCH 256
#define TT 576
#define NH 8
#define QSCALE 0.17677669529663687f
#define GN_EPS 1e-5f

__device__ float g_qkv[BB * 768 * TT];
__device__ float g_kt[BB * NH * TT * 32];
__device__ float g_vt[BB * NH * TT * 32];
__device__ float g_bd2[BB * NH * TT * 24];
__device__ float g_P[48 * 256];
__device__ float g_att[BB * TT * CCH];
__device__ float g_y[BB * CCH * TT];
__device__ float g_mu[BB * 16];
__device__ float g_rstd[BB * 16];

__global__ void k0_prep(const float* __restrict__ rh_v, const float* __restrict__ rw_v) {
    int idx = blockIdx.x * 256 + threadIdx.x;   // 48*256
    int m = idx >> 8, rest = idx & 255;
    g_P[idx] = (m > 0) ? (rh_v[(m - 1) * 256 + rest] + rw_v[(m - 1) * 256 + rest]) : 0.f;
}

// generic 64x64-tile fp32 GEMM body: out[o][i] = sum_c W[o][c]*X[c][i]
__device__ __forceinline__ void gemm_tile(const float* __restrict__ W, const float* __restrict__ Xc,
                                          int o0, int Xstride, float acc[4][4], int tid,
                                          float As[16][68], float Bs[16][68], bool x_rowmajor_ci,
                                          const float* __restrict__ Xrm, int i0) {
    int tx = tid % 16, ty = tid / 16;
    for (int c0 = 0; c0 < 256; c0 += 16) {
        int row = tid >> 2, cc = (tid & 3) * 4;
        float4 wv = *(const float4*)&W[(o0 + row) * 256 + c0 + cc];
        As[cc + 0][row] = wv.x; As[cc + 1][row] = wv.y;
        As[cc + 2][row] = wv.z; As[cc + 3][row] = wv.w;
        if (!x_rowmajor_ci) {
            float4 xv = *(const float4*)&Xrm[(i0 + row) * 256 + c0 + cc];
            Bs[cc + 0][row] = xv.x; Bs[cc + 1][row] = xv.y;
            Bs[cc + 2][row] = xv.z; Bs[cc + 3][row] = xv.w;
        } else {
            int cr = tid >> 4, i4 = (tid & 15) * 4;
            *(float4*)&Bs[cr][i4] = *(const float4*)&Xc[(c0 + cr) * Xstride + i0 + i4];
        }
        __syncthreads();
#pragma unroll
        for (int kk = 0; kk < 16; kk++) {
            float a[4], bv[4];
            *(float4*)a  = *(const float4*)&As[kk][ty * 4];
            *(float4*)bv = *(const float4*)&Bs[kk][tx * 4];
#pragma unroll
            for (int r = 0; r < 4; r++)
#pragma unroll
                for (int s = 0; s < 4; s++) acc[r][s] += a[r] * bv[s];
        }
        __syncthreads();
    }
}

__global__ __launch_bounds__(256) void k1_qkv(const float* __restrict__ x,
                                              const float* __restrict__ w,
                                              const float* __restrict__ bias) {
    int b = blockIdx.z, o0 = blockIdx.y * 64, i0 = blockIdx.x * 64;
    __shared__ float As[16][68], Bs[16][68];
    float acc[4][4] = {};
    int tid = threadIdx.x, tx = tid % 16, ty = tid / 16;
    gemm_tile(w, x + (size_t)b * CCH * TT, o0, TT, acc, tid, As, Bs, true, nullptr, i0);
#pragma unroll
    for (int r = 0; r < 4; r++) {
        int o = o0 + ty * 4 + r;
        float bv = bias[o];
        float4 out = make_float4(acc[r][0] + bv, acc[r][1] + bv, acc[r][2] + bv, acc[r][3] + bv);
        *(float4*)&g_qkv[((size_t)b * 768 + o) * TT + i0 + tx * 4] = out;
    }
}

__global__ void k1b_transpose() {
    int b = blockIdx.z, n = blockIdx.y, j0 = blockIdx.x * 32;
    __shared__ float tk[32][33], tv[32][33];
    int tx = threadIdx.x, ty = threadIdx.y;
#pragma unroll
    for (int r = 0; r < 4; r++) {
        int d = ty + 8 * r;
        tk[d][tx] = g_qkv[((size_t)b * 768 + 256 + n * 32 + d) * TT + j0 + tx];
        tv[d][tx] = g_qkv[((size_t)b * 768 + 512 + n * 32 + d) * TT + j0 + tx];
    }
    __syncthreads();
#pragma unroll
    for (int r = 0; r < 4; r++) {
        int jj = ty + 8 * r;
        size_t base = (((size_t)b * NH + n) * TT + j0 + jj) * 32 + tx;
        g_kt[base] = tk[tx][jj];
        g_vt[base] = tv[tx][jj];
    }
}

__global__ void k2_bd2(const float* __restrict__ rh_k, const float* __restrict__ rw_k) {
    extern __shared__ float Rs[];   // [n][47][33]
    int b = blockIdx.y, i0 = blockIdx.x * 64;
    int tid = threadIdx.x;
    for (int idx = tid; idx < 8 * 47 * 32; idx += 256) {
        int n = idx / (47 * 32), rem = idx % (47 * 32);
        int l = rem / 32, d = rem % 32;
        Rs[(n * 47 + l) * 33 + d] = rh_k[(l * 8 + n) * 32 + d] + rw_k[(l * 8 + n) * 32 + d];
    }
    __syncthreads();
    int il = tid % 64, slot = tid / 64;
    int ig = i0 + il;
    const float* qb = g_qkv + (size_t)b * 768 * TT;
    for (int idx = slot; idx < 8 * 24; idx += 4) {
        int n = idx / 24, c = idx % 24;
        int diff = c - ig;
        int fl = (diff >= 0) ? 0 : -((-diff + 47) / 48);
        int l = diff - 48 * fl;
        int iu = 12 + ig + fl;
        float acc = 0.f;
        if (l != 0) {
            const float* qr = qb + (size_t)(n * 32) * TT + iu;
            const float* rr = &Rs[(n * 47 + (l - 1)) * 33];
#pragma unroll
            for (int d = 0; d < 32; d++) acc += qr[(size_t)d * TT] * rr[d];
        }
        g_bd2[(((size_t)b * NH + n) * TT + ig) * 24 + c] = acc;
    }
}

// fused attention: block = (b, 16-row i-tile); softmax over head axis
__global__ __launch_bounds__(256) void k3_attn() {
    extern __shared__ float sm[];
    float* q_s  = sm;            // [8][16][32]
    float* z_s  = sm + 4096;     // [8][32][20]
    float* A_s  = sm + 9216;     // [8][16][24]
    float* bd_s = sm + 12288;    // [8][16][24]
    int b = blockIdx.y, i0 = blockIdx.x * 16;
    int tid = threadIdx.x, warp = tid >> 5, lane = tid & 31;

    {
        const float* qrow = g_qkv + ((size_t)b * 768 + tid) * TT + i0;
#pragma unroll
        for (int ii = 0; ii < 16; ii++) q_s[(warp * 16 + ii) * 32 + lane] = qrow[ii];
    }
    for (int idx = tid; idx < 8 * 16 * 24; idx += 256) {
        int n = idx / 384, r = idx % 384, ii = r / 24, c = r % 24;
        bd_s[idx] = g_bd2[(((size_t)b * NH + n) * TT + i0 + ii) * 24 + c];
        A_s[idx] = 0.f;
    }
    float acc[16];
#pragma unroll
    for (int ii = 0; ii < 16; ii++) acc[ii] = 0.f;
    __syncthreads();

    for (int jt = 0; jt < TT; jt += 32) {
        {   // logits: warp = head, lane = j
            int n = warp, j = jt + lane, c = j % 24;
            const float4* kp = (const float4*)(g_kt + (((size_t)b * NH + n) * TT + j) * 32);
            float4 kr[8];
#pragma unroll
            for (int q4 = 0; q4 < 8; q4++) kr[q4] = kp[q4];
#pragma unroll
            for (int ii = 0; ii < 16; ii++) {
                const float4* qv = (const float4*)&q_s[(n * 16 + ii) * 32];
                float s = 0.f;
#pragma unroll
                for (int q4 = 0; q4 < 8; q4++) {
                    float4 qq = qv[q4];
                    s += qq.x * kr[q4].x + qq.y * kr[q4].y + qq.z * kr[q4].z + qq.w * kr[q4].w;
                }
                z_s[(n * 32 + lane) * 20 + ii] = s + bd_s[(n * 16 + ii) * 24 + c];
            }
        }
        __syncthreads();
        {   // softmax over heads at each (i,j)
            int j = tid & 31, ibase = tid >> 5;
            int c = (jt + j) % 24;
#pragma unroll
            for (int p = 0; p < 2; p++) {
                int i = ibase + 8 * p;
                float zz[8];
#pragma unroll
                for (int n = 0; n < 8; n++) zz[n] = z_s[(n * 32 + j) * 20 + i] * QSCALE;
                float mx = zz[0];
#pragma unroll
                for (int n = 1; n < 8; n++) mx = fmaxf(mx, zz[n]);
                float e[8], s = 0.f;
#pragma unroll
                for (int n = 0; n < 8; n++) { e[n] = __expf(zz[n] - mx); s += e[n]; }
                float inv = 1.f / s;
#pragma unroll
                for (int n = 0; n < 8; n++) {
                    float a = e[n] * inv;
                    z_s[(n * 32 + j) * 20 + i] = a;
                    atomicAdd(&A_s[(n * 16 + i) * 24 + c], a);
                }
            }
        }
        __syncthreads();
        {   // attn @ v: warp = head, lane = d
            int n = warp, d = lane;
            const float* vp = g_vt + (((size_t)b * NH + n) * TT + jt) * 32 + d;
#pragma unroll 4
            for (int jj = 0; jj < 32; jj++) {
                float v = vp[jj * 32];
                const float4* ap = (const float4*)&z_s[(n * 32 + jj) * 20];
#pragma unroll
                for (int q4 = 0; q4 < 4; q4++) {
                    float4 a = ap[q4];
                    acc[q4 * 4 + 0] += a.x * v; acc[q4 * 4 + 1] += a.y * v;
                    acc[q4 * 4 + 2] += a.z * v; acc[q4 * 4 + 3] += a.w * v;
                }
            }
        }
        __syncthreads();
    }
    {   // epilogue: positional-value term
        int n = warp, d = lane;
#pragma unroll
        for (int ii = 0; ii < 16; ii++) {
            int ig = i0 + ii;
            float o2 = 0.f;
#pragma unroll
            for (int c = 0; c < 24; c++) {
                int m = (c - ig) % 48; if (m < 0) m += 48;
                o2 += A_s[(n * 16 + ii) * 24 + c] * g_P[m * 256 + n * 32 + d];
            }
            g_att[((size_t)b * TT + ig) * CCH + n * 32 + d] = acc[ii] + o2;
        }
    }
}

__global__ __launch_bounds__(256) void k4_fc(const float* __restrict__ x,
                                             const float* __restrict__ w,
                                             const float* __restrict__ bias) {
    int b = blockIdx.z, o0 = blockIdx.y * 64, i0 = blockIdx.x * 64;
    __shared__ float As[16][68], Bs[16][68];
    float acc[4][4] = {};
    int tid = threadIdx.x, tx = tid % 16, ty = tid / 16;
    gemm_tile(w, nullptr, o0, 0, acc, tid, As, Bs, false, g_att + (size_t)b * TT * CCH, i0);
#pragma unroll
    for (int r = 0; r < 4; r++) {
        int o = o0 + ty * 4 + r;
        float bv = bias[o];
        float4 xv = *(const float4*)&x[((size_t)b * CCH + o) * TT + i0 + tx * 4];
        float4 out = make_float4(acc[r][0] + bv + xv.x, acc[r][1] + bv + xv.y,
                                 acc[r][2] + bv + xv.z, acc[r][3] + bv + xv.w);
        *(float4*)&g_y[((size_t)b * CCH + o) * TT + i0 + tx * 4] = out;
    }
}

__global__ void k5_gnstats() {
    int bid = blockIdx.x, b = bid >> 4, g = bid & 15;
    const float* yp = g_y + ((size_t)(b * CCH + g * 16)) * TT;
    int tid = threadIdx.x;
    float s = 0.f, sq = 0.f;
    for (int idx = tid; idx < 16 * TT; idx += 256) { float v = yp[idx]; s += v; sq += v * v; }
#pragma unroll
    for (int off = 16; off > 0; off >>= 1) {
        s  += __shfl_down_sync(0xffffffffu, s, off);
        sq += __shfl_down_sync(0xffffffffu, sq, off);
    }
    __shared__ float rs[8], rq[8];
    if ((tid & 31) == 0) { rs[tid >> 5] = s; rq[tid >> 5] = sq; }
    __syncthreads();
    if (tid == 0) {
        float S = 0.f, Q = 0.f;
#pragma unroll
        for (int w = 0; w < 8; w++) { S += rs[w]; Q += rq[w]; }
        float mu = S / 9216.f;
        float var = Q / 9216.f - mu * mu;
        g_mu[bid] = mu;
        g_rstd[bid] = rsqrtf(var + GN_EPS);
    }
}

__global__ void k6_gnapply(float* __restrict__ out, const float* __restrict__ gw,
                           const float* __restrict__ gb) {
    int idx = blockIdx.x * 256 + threadIdx.x;
    int o = (idx / TT) & 255;
    int b = idx / (TT * CCH);
    float mu = g_mu[b * 16 + (o >> 4)], rstd = g_rstd[b * 16 + (o >> 4)];
    out[idx] = (g_y[idx] - mu) * rstd * gw[o] + gb[o];
}

extern "C" void kernel_launch(void* const* d_in, const int* in_sizes, int n_in,
                              void* d_out, int out_size) {
    const float* x     = (const float*)d_in[0];
    const float* qkv_w = (const float*)d_in[1];
    const float* qkv_b = (const float*)d_in[2];
    const float* rh_k  = (const float*)d_in[3];
    const float* rw_k  = (const float*)d_in[4];
    const float* rh_v  = (const float*)d_in[5];
    const float* rw_v  = (const float*)d_in[6];
    const float* fc_w  = (const float*)d_in[7];
    const float* fc_b  = (const float*)d_in[8];
    const float* gn_w  = (const float*)d_in[9];
    const float* gn_b  = (const float*)d_in[10];
    float* out = (float*)d_out;

    cudaFuncSetAttribute(k2_bd2, cudaFuncAttributeMaxDynamicSharedMemorySize, 49632);
    cudaFuncSetAttribute(k3_attn, cudaFuncAttributeMaxDynamicSharedMemorySize, 61440);

    k0_prep<<<48, 256>>>(rh_v, rw_v);
    k1_qkv<<<dim3(9, 12, BB), 256>>>(x, qkv_w, qkv_b);
    k1b_transpose<<<dim3(18, NH, BB), dim3(32, 8)>>>();
    k2_bd2<<<dim3(9, BB), 256, 49632>>>(rh_k, rw_k);
    k3_attn<<<dim3(36, BB), 256, 61440>>>();
    k4_fc<<<dim3(9, 4, BB), 256>>>(x, fc_w, fc_b);
    k5_gnstats<<<256, 256>>>();
    k6_gnapply<<<9216, 256>>>(out, gn_w, gn_b);
}